// round 1
// baseline (speedup 1.0000x reference)
#include <cuda_runtime.h>
#include <cuda_bf16.h>
#include <cstdint>

// Problem constants
#define BB 8
#define SEQ 1024
#define CC 512
#define NH 8
#define HD 64
#define NG 32
#define GSZ 16
#define C3 1536

// Scratch (static device allocations are the sanctioned mechanism)
__device__ float g_xn[BB * SEQ * CC];     // normalized x      (16.8 MB)
__device__ float g_qkv[BB * SEQ * C3];    // qkv projection    (50.3 MB)
__device__ float g_attn[BB * SEQ * CC];   // attention output  (16.8 MB)

// ---------------------------------------------------------------------------
// f32x2 packed helpers (Blackwell fp32x2 pipe; ptxas never auto-fuses these)
// ---------------------------------------------------------------------------
__device__ __forceinline__ void fma2(unsigned long long& c, unsigned long long a, unsigned long long b) {
    asm("fma.rn.f32x2 %0, %1, %2, %0;" : "+l"(c) : "l"(a), "l"(b));
}
__device__ __forceinline__ unsigned long long pack_dup(float x) {
    unsigned long long r; asm("mov.b64 %0, {%1,%1};" : "=l"(r) : "f"(x)); return r;
}
__device__ __forceinline__ unsigned long long pack2(float x, float y) {
    unsigned long long r; asm("mov.b64 %0, {%1,%2};" : "=l"(r) : "f"(x), "f"(y)); return r;
}
__device__ __forceinline__ float2 unpack2(unsigned long long v) {
    float2 f; asm("mov.b64 {%0,%1}, %2;" : "=f"(f.x), "=f"(f.y) : "l"(v)); return f;
}
__device__ __forceinline__ void mul2(unsigned long long& c, unsigned long long a, unsigned long long b) {
    asm("mul.rn.f32x2 %0, %1, %2;" : "=l"(c) : "l"(a), "l"(b));
}

// ---------------------------------------------------------------------------
// Kernel 1: GroupNorm. One CTA per (batch, group). 256 threads.
// Reduce 1024 spatial x 16 channels, then normalize into g_xn.
// ---------------------------------------------------------------------------
__global__ __launch_bounds__(256) void gn_kernel(
    const float* __restrict__ x, const float* __restrict__ gamma,
    const float* __restrict__ beta, float* __restrict__ xn)
{
    int bg = blockIdx.x;             // 0..255
    int b = bg >> 5, g = bg & 31;
    const float* base = x + (size_t)b * SEQ * CC + g * GSZ;
    int tid = threadIdx.x;

    float sum = 0.f, sq = 0.f;
    #pragma unroll
    for (int i = 0; i < 4; i++) {
        int s = tid + i * 256;
        const float4* p = reinterpret_cast<const float4*>(base + (size_t)s * CC);
        #pragma unroll
        for (int v4 = 0; v4 < 4; v4++) {
            float4 v = p[v4];
            sum += v.x + v.y + v.z + v.w;
            sq  += v.x * v.x + v.y * v.y + v.z * v.z + v.w * v.w;
        }
    }
    // block reduce
    #pragma unroll
    for (int off = 16; off; off >>= 1) {
        sum += __shfl_xor_sync(0xFFFFFFFFu, sum, off);
        sq  += __shfl_xor_sync(0xFFFFFFFFu, sq, off);
    }
    __shared__ float red[2][8];
    __shared__ float stats[2];
    int wid = tid >> 5, lid = tid & 31;
    if (lid == 0) { red[0][wid] = sum; red[1][wid] = sq; }
    __syncthreads();
    if (tid == 0) {
        float S = 0.f, Q = 0.f;
        #pragma unroll
        for (int w = 0; w < 8; w++) { S += red[0][w]; Q += red[1][w]; }
        float mu = S * (1.f / 16384.f);
        float var = Q * (1.f / 16384.f) - mu * mu;
        stats[0] = mu;
        stats[1] = rsqrtf(var + 1e-6f);
    }
    __syncthreads();
    float mu = stats[0], rstd = stats[1];

    float ga[GSZ], be[GSZ];
    #pragma unroll
    for (int c = 0; c < GSZ; c++) {
        ga[c] = gamma[g * GSZ + c] * rstd;
        be[c] = beta[g * GSZ + c];
    }
    float* obase = xn + (size_t)b * SEQ * CC + g * GSZ;
    #pragma unroll
    for (int i = 0; i < 4; i++) {
        int s = tid + i * 256;
        const float4* p = reinterpret_cast<const float4*>(base + (size_t)s * CC);
        float4* q = reinterpret_cast<float4*>(obase + (size_t)s * CC);
        #pragma unroll
        for (int v4 = 0; v4 < 4; v4++) {
            float4 v = p[v4];
            int c = v4 * 4;
            v.x = (v.x - mu) * ga[c + 0] + be[c + 0];
            v.y = (v.y - mu) * ga[c + 1] + be[c + 1];
            v.z = (v.z - mu) * ga[c + 2] + be[c + 2];
            v.w = (v.w - mu) * ga[c + 3] + be[c + 3];
            q[v4] = v;
        }
    }
}

// ---------------------------------------------------------------------------
// Kernel 2/4: tiled GEMM  C[M,N] = A[M,512] * B[512,N] + bias (+ residual)
// BM=BN=128, BK=16, 256 threads, 8x8 micro-tile with f32x2 packed FMAs.
// Micro-column mapping: thread tx owns n = tx*2 + j*32 (j=0..3), pairs of 2 —
// conflict-free LDS.64 from Bs (32 consecutive floats per j across 16 tx).
// ---------------------------------------------------------------------------
__global__ __launch_bounds__(256) void gemm_kernel(
    const float* __restrict__ A, const float* __restrict__ B,
    const float* __restrict__ bias, const float* __restrict__ R,
    float* __restrict__ C, int N)
{
    const int K = 512;
    __shared__ float As[16][128];   // [k][m]
    __shared__ float Bs[16][128];   // [k][n]
    int bm = blockIdx.y * 128;
    int bn = blockIdx.x * 128;
    int tid = threadIdx.x;
    int tx = tid & 15;   // micro column group
    int ty = tid >> 4;   // micro row group (8 rows: ty*8 .. ty*8+7)

    unsigned long long c2[8][4];
    #pragma unroll
    for (int i = 0; i < 8; i++)
        #pragma unroll
        for (int j = 0; j < 4; j++) c2[i][j] = 0ULL;

    int a_r = tid >> 2;            // 0..63
    int a_c = (tid & 3) << 2;      // 0,4,8,12
    int b_r = tid >> 5;            // 0..7
    int b_c = (tid & 31) << 2;     // 0..124

    for (int kt = 0; kt < K; kt += 16) {
        #pragma unroll
        for (int hh = 0; hh < 2; hh++) {
            int r = a_r + hh * 64;
            float4 v = *reinterpret_cast<const float4*>(A + (size_t)(bm + r) * K + kt + a_c);
            As[a_c + 0][r] = v.x; As[a_c + 1][r] = v.y;
            As[a_c + 2][r] = v.z; As[a_c + 3][r] = v.w;
        }
        #pragma unroll
        for (int hh = 0; hh < 2; hh++) {
            int r = b_r + hh * 8;
            *reinterpret_cast<float4*>(&Bs[r][b_c]) =
                *reinterpret_cast<const float4*>(B + (size_t)(kt + r) * N + bn + b_c);
        }
        __syncthreads();
        #pragma unroll
        for (int kk = 0; kk < 16; kk++) {
            unsigned long long b2[4];
            #pragma unroll
            for (int j = 0; j < 4; j++)
                b2[j] = *reinterpret_cast<const unsigned long long*>(&Bs[kk][tx * 2 + j * 32]);
            #pragma unroll
            for (int i = 0; i < 8; i++) {
                unsigned long long a2 = pack_dup(As[kk][ty * 8 + i]);
                #pragma unroll
                for (int j = 0; j < 4; j++) fma2(c2[i][j], a2, b2[j]);
            }
        }
        __syncthreads();
    }
    // epilogue
    #pragma unroll
    for (int i = 0; i < 8; i++) {
        int m = bm + ty * 8 + i;
        #pragma unroll
        for (int j = 0; j < 4; j++) {
            int n = bn + tx * 2 + j * 32;
            float2 v = unpack2(c2[i][j]);
            float r0 = bias[n], r1 = bias[n + 1];
            if (R) {
                r0 += R[(size_t)m * N + n];
                r1 += R[(size_t)m * N + n + 1];
            }
            C[(size_t)m * N + n]     = v.x + r0;
            C[(size_t)m * N + n + 1] = v.y + r1;
        }
    }
}

// ---------------------------------------------------------------------------
// Kernel 3: flash attention (fp32). One CTA per (batch, head, 128-row q-tile).
// 128 threads, one query row per thread; q/o/s register-resident (f32x2).
// K/V staged 32x64 in smem; inner reads are warp-uniform broadcasts (N=1).
// scale: (q*s)·(k*s) with s=1/8 -> fold 1/64 into q.
// ---------------------------------------------------------------------------
__global__ __launch_bounds__(128, 2) void attn_kernel(
    const float* __restrict__ qkv, float* __restrict__ out)
{
    __shared__ float Ks[32][64];
    __shared__ float Vs[32][64];
    int b = blockIdx.z, h = blockIdx.y, qt = blockIdx.x;
    int tid = threadIdx.x;
    int row = qt * 128 + tid;

    const float* qptr = qkv + (size_t)(b * SEQ + row) * C3 + h * HD;
    unsigned long long q2[32], o2[32];
    const float qscale = 1.0f / 64.0f;
    #pragma unroll
    for (int d = 0; d < 32; d++) {
        float2 v = reinterpret_cast<const float2*>(qptr)[d];
        q2[d] = pack2(v.x * qscale, v.y * qscale);
        o2[d] = 0ULL;
    }
    float m = -1e30f, l = 0.f;

    const float* kbase = qkv + (size_t)b * SEQ * C3 + CC + h * HD;

    for (int kt = 0; kt < 32; kt++) {
        // cooperative load of K and V tiles (32 rows x 64)
        #pragma unroll
        for (int i = 0; i < 4; i++) {
            int idx = tid + i * 128;                 // 0..511 float4 slots
            int r = idx >> 4, c4 = (idx & 15) << 2;
            const float* src = kbase + (size_t)(kt * 32 + r) * C3 + c4;
            *reinterpret_cast<float4*>(&Ks[r][c4]) = *reinterpret_cast<const float4*>(src);
            *reinterpret_cast<float4*>(&Vs[r][c4]) = *reinterpret_cast<const float4*>(src + CC);
        }
        __syncthreads();

        float s[32];
        #pragma unroll
        for (int j = 0; j < 32; j++) {
            unsigned long long acc = 0ULL;
            const unsigned long long* kr = reinterpret_cast<const unsigned long long*>(Ks[j]);
            #pragma unroll
            for (int d = 0; d < 32; d++) fma2(acc, q2[d], kr[d]);
            float2 a = unpack2(acc);
            s[j] = a.x + a.y;
        }
        float tmax = m;
        #pragma unroll
        for (int j = 0; j < 32; j++) tmax = fmaxf(tmax, s[j]);
        float corr = __expf(m - tmax);
        m = tmax;
        l *= corr;
        unsigned long long corr2 = pack_dup(corr);
        #pragma unroll
        for (int d = 0; d < 32; d++) mul2(o2[d], o2[d], corr2);

        #pragma unroll
        for (int j = 0; j < 32; j++) {
            float p = __expf(s[j] - m);
            l += p;
            unsigned long long p2 = pack_dup(p);
            const unsigned long long* vr = reinterpret_cast<const unsigned long long*>(Vs[j]);
            #pragma unroll
            for (int d = 0; d < 32; d++) fma2(o2[d], p2, vr[d]);
        }
        __syncthreads();
    }

    float inv = 1.0f / l;
    float* optr = out + (size_t)(b * SEQ + row) * CC + h * HD;
    #pragma unroll
    for (int d = 0; d < 32; d++) {
        float2 v = unpack2(o2[d]);
        v.x *= inv; v.y *= inv;
        reinterpret_cast<float2*>(optr)[d] = v;
    }
}

// ---------------------------------------------------------------------------
// Launch
// ---------------------------------------------------------------------------
extern "C" void kernel_launch(void* const* d_in, const int* in_sizes, int n_in,
                              void* d_out, int out_size)
{
    const float* x        = (const float*)d_in[0];
    const float* gn_scale = (const float*)d_in[1];
    const float* gn_bias  = (const float*)d_in[2];
    const float* w_qkv    = (const float*)d_in[3];
    const float* b_qkv    = (const float*)d_in[4];
    const float* w_out    = (const float*)d_in[5];
    const float* b_out    = (const float*)d_in[6];
    float* out            = (float*)d_out;

    float* xn;   cudaGetSymbolAddress((void**)&xn,   g_xn);
    float* qkv;  cudaGetSymbolAddress((void**)&qkv,  g_qkv);
    float* attn; cudaGetSymbolAddress((void**)&attn, g_attn);

    // 1) GroupNorm
    gn_kernel<<<BB * NG, 256>>>(x, gn_scale, gn_bias, xn);

    // 2) QKV projection: (8192 x 1536) = xn (8192x512) @ w_qkv (512x1536) + b
    {
        dim3 grid(C3 / 128, (BB * SEQ) / 128);
        gemm_kernel<<<grid, 256>>>(xn, w_qkv, b_qkv, nullptr, qkv, C3);
    }

    // 3) Attention
    {
        dim3 grid(SEQ / 128, NH, BB);
        attn_kernel<<<grid, 128>>>(qkv, attn);
    }

    // 4) Output projection + bias + residual -> d_out
    {
        dim3 grid(CC / 128, (BB * SEQ) / 128);
        gemm_kernel<<<grid, 256>>>(attn, w_out, b_out, x, out, CC);
    }
}

// round 4
// speedup vs baseline: 1.4163x; 1.4163x over previous
#include <cuda_runtime.h>
#include <cuda_fp16.h>
#include <cstdint>

// Problem constants
#define BB 8
#define SEQ 1024
#define CC 512
#define NH 8
#define HD 64
#define NG 32
#define GSZ 16
#define C3 1536

// Scratch
__device__ __half g_xn_h[BB * SEQ * CC];    // normalized x (fp16)
__device__ float  g_qkv[BB * SEQ * C3];     // qkv projection (fp32)
__device__ __half g_attn_h[BB * SEQ * CC];  // attention output (fp16)
__device__ __half g_wth_qkv[C3 * CC];       // w_qkv^T [N,K] fp16
__device__ __half g_wth_out[CC * CC];       // w_out^T [N,K] fp16

// ---------------------------------------------------------------------------
// helpers
// ---------------------------------------------------------------------------
__device__ __forceinline__ void fma2(unsigned long long& c, unsigned long long a, unsigned long long b) {
    asm("fma.rn.f32x2 %0, %1, %2, %0;" : "+l"(c) : "l"(a), "l"(b));
}
__device__ __forceinline__ unsigned long long pack_dup(float x) {
    unsigned long long r; asm("mov.b64 %0, {%1,%1};" : "=l"(r) : "f"(x)); return r;
}
__device__ __forceinline__ unsigned long long pack2(float x, float y) {
    unsigned long long r; asm("mov.b64 %0, {%1,%2};" : "=l"(r) : "f"(x), "f"(y)); return r;
}
__device__ __forceinline__ float2 unpack2(unsigned long long v) {
    float2 f; asm("mov.b64 {%0,%1}, %2;" : "=f"(f.x), "=f"(f.y) : "l"(v)); return f;
}
__device__ __forceinline__ void mul2(unsigned long long& c, unsigned long long a, unsigned long long b) {
    asm("mul.rn.f32x2 %0, %1, %2;" : "=l"(c) : "l"(a), "l"(b));
}
__device__ __forceinline__ uint32_t smem_u32(const void* p) {
    uint32_t a; asm("{ .reg .u64 t; cvta.to.shared.u64 t, %1; cvt.u32.u64 %0, t; }" : "=r"(a) : "l"(p));
    return a;
}

#define CP_ASYNC16(sa, ga) \
    asm volatile("cp.async.cg.shared.global [%0], [%1], 16;" :: "r"(sa), "l"(ga))
#define CP_COMMIT() asm volatile("cp.async.commit_group;")
#define CP_WAIT(n)  asm volatile("cp.async.wait_group %0;" :: "n"(n))

#define LDMATRIX_X4(r0, r1, r2, r3, addr) \
    asm volatile("ldmatrix.sync.aligned.m8n8.x4.shared.b16 {%0,%1,%2,%3}, [%4];" \
        : "=r"(r0), "=r"(r1), "=r"(r2), "=r"(r3) : "r"(addr))

#define MMA16816(c, a0, a1, a2, a3, b0, b1) \
    asm volatile("mma.sync.aligned.m16n8k16.row.col.f32.f16.f16.f32 " \
        "{%0,%1,%2,%3}, {%4,%5,%6,%7}, {%8,%9}, {%0,%1,%2,%3};" \
        : "+f"((c)[0]), "+f"((c)[1]), "+f"((c)[2]), "+f"((c)[3]) \
        : "r"(a0), "r"(a1), "r"(a2), "r"(a3), "r"(b0), "r"(b1))

// ---------------------------------------------------------------------------
// Kernel 0: weight transpose + fp16 convert. W[512,N] -> Wt[N,512] (half)
// ---------------------------------------------------------------------------
__global__ __launch_bounds__(256) void wt_kernel(
    const float* __restrict__ W, __half* __restrict__ Wt, int N)
{
    __shared__ float t[32][33];
    int kb = blockIdx.y * 32, nb = blockIdx.x * 32;
    int tx = threadIdx.x, ty = threadIdx.y;   // 32 x 8
    #pragma unroll
    for (int i = 0; i < 32; i += 8)
        t[ty + i][tx] = W[(size_t)(kb + ty + i) * N + nb + tx];
    __syncthreads();
    #pragma unroll
    for (int i = 0; i < 32; i += 8)
        Wt[(size_t)(nb + ty + i) * 512 + kb + tx] = __float2half_rn(t[tx][ty + i]);
}

// ---------------------------------------------------------------------------
// Kernel 1: GroupNorm -> fp16 output
// ---------------------------------------------------------------------------
__global__ __launch_bounds__(256) void gn_kernel(
    const float* __restrict__ x, const float* __restrict__ gamma,
    const float* __restrict__ beta, __half* __restrict__ xn)
{
    int bg = blockIdx.x;
    int b = bg >> 5, g = bg & 31;
    const float* base = x + (size_t)b * SEQ * CC + g * GSZ;
    int tid = threadIdx.x;

    float sum = 0.f, sq = 0.f;
    #pragma unroll
    for (int i = 0; i < 4; i++) {
        int s = tid + i * 256;
        const float4* p = reinterpret_cast<const float4*>(base + (size_t)s * CC);
        #pragma unroll
        for (int v4 = 0; v4 < 4; v4++) {
            float4 v = p[v4];
            sum += v.x + v.y + v.z + v.w;
            sq  += v.x * v.x + v.y * v.y + v.z * v.z + v.w * v.w;
        }
    }
    #pragma unroll
    for (int off = 16; off; off >>= 1) {
        sum += __shfl_xor_sync(0xFFFFFFFFu, sum, off);
        sq  += __shfl_xor_sync(0xFFFFFFFFu, sq, off);
    }
    __shared__ float red[2][8];
    __shared__ float stats[2];
    int wid = tid >> 5, lid = tid & 31;
    if (lid == 0) { red[0][wid] = sum; red[1][wid] = sq; }
    __syncthreads();
    if (tid == 0) {
        float S = 0.f, Q = 0.f;
        #pragma unroll
        for (int w = 0; w < 8; w++) { S += red[0][w]; Q += red[1][w]; }
        float mu = S * (1.f / 16384.f);
        float var = Q * (1.f / 16384.f) - mu * mu;
        stats[0] = mu;
        stats[1] = rsqrtf(var + 1e-6f);
    }
    __syncthreads();
    float mu = stats[0], rstd = stats[1];

    float ga[GSZ], be[GSZ];
    #pragma unroll
    for (int c = 0; c < GSZ; c++) {
        ga[c] = gamma[g * GSZ + c] * rstd;
        be[c] = beta[g * GSZ + c];
    }
    __half* obase = xn + (size_t)b * SEQ * CC + g * GSZ;
    #pragma unroll
    for (int i = 0; i < 4; i++) {
        int s = tid + i * 256;
        const float4* p = reinterpret_cast<const float4*>(base + (size_t)s * CC);
        __half2* q = reinterpret_cast<__half2*>(obase + (size_t)s * CC);
        #pragma unroll
        for (int v4 = 0; v4 < 4; v4++) {
            float4 v = p[v4];
            int c = v4 * 4;
            float y0 = (v.x - mu) * ga[c + 0] + be[c + 0];
            float y1 = (v.y - mu) * ga[c + 1] + be[c + 1];
            float y2 = (v.z - mu) * ga[c + 2] + be[c + 2];
            float y3 = (v.w - mu) * ga[c + 3] + be[c + 3];
            q[v4 * 2 + 0] = __floats2half2_rn(y0, y1);
            q[v4 * 2 + 1] = __floats2half2_rn(y2, y3);
        }
    }
}

// ---------------------------------------------------------------------------
// Kernel 2: fp16 HMMA GEMM.  C[M,N] = A[M,512](h) @ Wt[N,512](h)^T + bias (+R)
// CTA 128x128, BK=32, cp.async double-buffer, 8 warps, warp tile 32x64.
// Smem row stride 40 halves (80B) -> ldmatrix conflict-free.
// ---------------------------------------------------------------------------
#define GSTRIDE 40

__global__ __launch_bounds__(256) void gemm_hmma(
    const __half* __restrict__ A, const __half* __restrict__ Wt,
    const float* __restrict__ bias, const float* __restrict__ R,
    float* __restrict__ C, int N)
{
    __shared__ __half As[2][128 * GSTRIDE];
    __shared__ __half Bs[2][128 * GSTRIDE];

    int tid = threadIdx.x;
    int lane = tid & 31;
    int wid = tid >> 5;
    int wm = (wid & 3) * 32;   // warp row offset
    int wn = (wid >> 2) * 64;  // warp col offset
    int bm = blockIdx.y * 128;
    int bn = blockIdx.x * 128;

    float c[2][8][4];
    #pragma unroll
    for (int mi = 0; mi < 2; mi++)
        #pragma unroll
        for (int ni = 0; ni < 8; ni++)
            #pragma unroll
            for (int k = 0; k < 4; k++) c[mi][ni][k] = 0.f;

    // stage loader: 512 chunks of 16B each for A and B
    auto stage = [&](int s, int buf) {
        const __half* Ag = A + (size_t)bm * 512 + s * 32;
        const __half* Bg = Wt + (size_t)bn * 512 + s * 32;
        #pragma unroll
        for (int i = 0; i < 2; i++) {
            int chunk = tid + i * 256;
            int r = chunk >> 2, cc = chunk & 3;
            uint32_t sa = smem_u32(&As[buf][r * GSTRIDE + cc * 8]);
            CP_ASYNC16(sa, Ag + (size_t)r * 512 + cc * 8);
            uint32_t sbb = smem_u32(&Bs[buf][r * GSTRIDE + cc * 8]);
            CP_ASYNC16(sbb, Bg + (size_t)r * 512 + cc * 8);
        }
    };

    stage(0, 0);
    CP_COMMIT();

    for (int s = 0; s < 16; s++) {
        int buf = s & 1;
        if (s + 1 < 16) {
            stage(s + 1, buf ^ 1);
            CP_COMMIT();
            CP_WAIT(1);
        } else {
            CP_WAIT(0);
        }
        __syncthreads();

        const __half* Ab = As[buf];
        const __half* Bb = Bs[buf];
        #pragma unroll
        for (int kk = 0; kk < 2; kk++) {
            uint32_t a[2][4];
            #pragma unroll
            for (int mi = 0; mi < 2; mi++) {
                int row = wm + mi * 16 + (lane & 7) + ((lane >> 3) & 1) * 8;
                int kc = kk * 16 + ((lane >> 4) & 1) * 8;
                uint32_t addr = smem_u32(&Ab[row * GSTRIDE + kc]);
                LDMATRIX_X4(a[mi][0], a[mi][1], a[mi][2], a[mi][3], addr);
            }
            uint32_t b[8][2];
            #pragma unroll
            for (int bi = 0; bi < 4; bi++) {
                int n = wn + bi * 16 + (lane & 7) + ((lane >> 4) & 1) * 8;
                int kc = kk * 16 + ((lane >> 3) & 1) * 8;
                uint32_t addr = smem_u32(&Bb[n * GSTRIDE + kc]);
                uint32_t r0, r1, r2, r3;
                LDMATRIX_X4(r0, r1, r2, r3, addr);
                b[bi * 2 + 0][0] = r0; b[bi * 2 + 0][1] = r1;
                b[bi * 2 + 1][0] = r2; b[bi * 2 + 1][1] = r3;
            }
            #pragma unroll
            for (int mi = 0; mi < 2; mi++)
                #pragma unroll
                for (int ni = 0; ni < 8; ni++)
                    MMA16816(c[mi][ni], a[mi][0], a[mi][1], a[mi][2], a[mi][3],
                             b[ni][0], b[ni][1]);
        }
        __syncthreads();
    }

    // epilogue
    #pragma unroll
    for (int mi = 0; mi < 2; mi++) {
        int r0 = bm + wm + mi * 16 + (lane >> 2);
        #pragma unroll
        for (int ni = 0; ni < 8; ni++) {
            int col = bn + wn + ni * 8 + (lane & 3) * 2;
            float bx = bias[col], by = bias[col + 1];
            float2 v0 = make_float2(c[mi][ni][0] + bx, c[mi][ni][1] + by);
            float2 v1 = make_float2(c[mi][ni][2] + bx, c[mi][ni][3] + by);
            if (R) {
                const float2 ra = *reinterpret_cast<const float2*>(R + (size_t)r0 * N + col);
                const float2 rb = *reinterpret_cast<const float2*>(R + (size_t)(r0 + 8) * N + col);
                v0.x += ra.x; v0.y += ra.y;
                v1.x += rb.x; v1.y += rb.y;
            }
            *reinterpret_cast<float2*>(C + (size_t)r0 * N + col) = v0;
            *reinterpret_cast<float2*>(C + (size_t)(r0 + 8) * N + col) = v1;
        }
    }
}

// ---------------------------------------------------------------------------
// Kernel 3: flash attention (fp32 SIMT), output fp16 for out-proj
// ---------------------------------------------------------------------------
__global__ __launch_bounds__(128, 2) void attn_kernel(
    const float* __restrict__ qkv, __half* __restrict__ out)
{
    __shared__ float Ks[32][64];
    __shared__ float Vs[32][64];
    int b = blockIdx.z, h = blockIdx.y, qt = blockIdx.x;
    int tid = threadIdx.x;
    int row = qt * 128 + tid;

    const float* qptr = qkv + (size_t)(b * SEQ + row) * C3 + h * HD;
    unsigned long long q2[32], o2[32];
    const float qscale = 1.0f / 64.0f;
    #pragma unroll
    for (int d = 0; d < 32; d++) {
        float2 v = reinterpret_cast<const float2*>(qptr)[d];
        q2[d] = pack2(v.x * qscale, v.y * qscale);
        o2[d] = 0ULL;
    }
    float m = -1e30f, l = 0.f;

    const float* kbase = qkv + (size_t)b * SEQ * C3 + CC + h * HD;

    for (int kt = 0; kt < 32; kt++) {
        #pragma unroll
        for (int i = 0; i < 4; i++) {
            int idx = tid + i * 128;
            int r = idx >> 4, c4 = (idx & 15) << 2;
            const float* src = kbase + (size_t)(kt * 32 + r) * C3 + c4;
            *reinterpret_cast<float4*>(&Ks[r][c4]) = *reinterpret_cast<const float4*>(src);
            *reinterpret_cast<float4*>(&Vs[r][c4]) = *reinterpret_cast<const float4*>(src + CC);
        }
        __syncthreads();

        float s[32];
        #pragma unroll
        for (int j = 0; j < 32; j++) {
            unsigned long long acc = 0ULL;
            const unsigned long long* kr = reinterpret_cast<const unsigned long long*>(Ks[j]);
            #pragma unroll
            for (int d = 0; d < 32; d++) fma2(acc, q2[d], kr[d]);
            float2 a = unpack2(acc);
            s[j] = a.x + a.y;
        }
        float tmax = m;
        #pragma unroll
        for (int j = 0; j < 32; j++) tmax = fmaxf(tmax, s[j]);
        float corr = __expf(m - tmax);
        m = tmax;
        l *= corr;
        unsigned long long corr2 = pack_dup(corr);
        #pragma unroll
        for (int d = 0; d < 32; d++) mul2(o2[d], o2[d], corr2);

        #pragma unroll
        for (int j = 0; j < 32; j++) {
            float p = __expf(s[j] - m);
            l += p;
            unsigned long long p2 = pack_dup(p);
            const unsigned long long* vr = reinterpret_cast<const unsigned long long*>(Vs[j]);
            #pragma unroll
            for (int d = 0; d < 32; d++) fma2(o2[d], p2, vr[d]);
        }
        __syncthreads();
    }

    float inv = 1.0f / l;
    __half2* optr = reinterpret_cast<__half2*>(out + (size_t)(b * SEQ + row) * CC + h * HD);
    #pragma unroll
    for (int d = 0; d < 32; d++) {
        float2 v = unpack2(o2[d]);
        optr[d] = __floats2half2_rn(v.x * inv, v.y * inv);
    }
}

// ---------------------------------------------------------------------------
// Launch
// ---------------------------------------------------------------------------
extern "C" void kernel_launch(void* const* d_in, const int* in_sizes, int n_in,
                              void* d_out, int out_size)
{
    const float* x        = (const float*)d_in[0];
    const float* gn_scale = (const float*)d_in[1];
    const float* gn_bias  = (const float*)d_in[2];
    const float* w_qkv    = (const float*)d_in[3];
    const float* b_qkv    = (const float*)d_in[4];
    const float* w_out    = (const float*)d_in[5];
    const float* b_out    = (const float*)d_in[6];
    float* out            = (float*)d_out;

    __half* xn;   cudaGetSymbolAddress((void**)&xn,   g_xn_h);
    float*  qkv;  cudaGetSymbolAddress((void**)&qkv,  g_qkv);
    __half* attn; cudaGetSymbolAddress((void**)&attn, g_attn_h);
    __half* wtq;  cudaGetSymbolAddress((void**)&wtq,  g_wth_qkv);
    __half* wto;  cudaGetSymbolAddress((void**)&wto,  g_wth_out);

    // 0) weight transposes (fp16)
    {
        dim3 blk(32, 8);
        wt_kernel<<<dim3(C3 / 32, 16), blk>>>(w_qkv, wtq, C3);
        wt_kernel<<<dim3(CC / 32, 16), blk>>>(w_out, wto, CC);
    }

    // 1) GroupNorm -> fp16
    gn_kernel<<<BB * NG, 256>>>(x, gn_scale, gn_bias, xn);

    // 2) QKV projection (HMMA fp16)
    gemm_hmma<<<dim3(C3 / 128, (BB * SEQ) / 128), 256>>>(xn, wtq, b_qkv, nullptr, qkv, C3);

    // 3) Attention (fp32 SIMT)
    attn_kernel<<<dim3(SEQ / 128, NH, BB), 128>>>(qkv, attn);

    // 4) Output projection + bias + residual (HMMA fp16)
    gemm_hmma<<<dim3(CC / 128, (BB * SEQ) / 128), 256>>>(attn, wto, b_out, x, out, CC);
}

// round 7
// speedup vs baseline: 4.9913x; 3.5241x over previous
#include <cuda_runtime.h>
#include <cuda_fp16.h>
#include <cstdint>

// Problem constants
#define BB 8
#define SEQ 1024
#define CC 512
#define NH 8
#define HD 64
#define NG 32
#define GSZ 16
#define C3 1536

// Scratch
__device__ __half g_xn_h[BB * SEQ * CC];    // normalized x (fp16)
__device__ __half g_qkv_h[BB * SEQ * C3];   // qkv projection (fp16)
__device__ __half g_attn_h[BB * SEQ * CC];  // attention output (fp16)
__device__ __half g_wth_qkv[C3 * CC];       // w_qkv^T [N,K] fp16
__device__ __half g_wth_out[CC * CC];       // w_out^T [N,K] fp16

// ---------------------------------------------------------------------------
// helpers
// ---------------------------------------------------------------------------
__device__ __forceinline__ uint32_t smem_u32(const void* p) {
    uint32_t a; asm("{ .reg .u64 t; cvta.to.shared.u64 t, %1; cvt.u32.u64 %0, t; }" : "=r"(a) : "l"(p));
    return a;
}
__device__ __forceinline__ uint32_t f22u(float a, float b) {
    __half2 h = __floats2half2_rn(a, b);
    return *reinterpret_cast<uint32_t*>(&h);
}

#define CP_ASYNC16(sa, ga) \
    asm volatile("cp.async.cg.shared.global [%0], [%1], 16;" :: "r"(sa), "l"(ga))
#define CP_COMMIT() asm volatile("cp.async.commit_group;")
#define CP_WAIT(n)  asm volatile("cp.async.wait_group %0;" :: "n"(n))

#define LDMATRIX_X4(r0, r1, r2, r3, addr) \
    asm volatile("ldmatrix.sync.aligned.m8n8.x4.shared.b16 {%0,%1,%2,%3}, [%4];" \
        : "=r"(r0), "=r"(r1), "=r"(r2), "=r"(r3) : "r"(addr))

#define LDMATRIX_X4_T(r0, r1, r2, r3, addr) \
    asm volatile("ldmatrix.sync.aligned.m8n8.x4.trans.shared.b16 {%0,%1,%2,%3}, [%4];" \
        : "=r"(r0), "=r"(r1), "=r"(r2), "=r"(r3) : "r"(addr))

#define MMA16816(c, a0, a1, a2, a3, b0, b1) \
    asm volatile("mma.sync.aligned.m16n8k16.row.col.f32.f16.f16.f32 " \
        "{%0,%1,%2,%3}, {%4,%5,%6,%7}, {%8,%9}, {%0,%1,%2,%3};" \
        : "+f"((c)[0]), "+f"((c)[1]), "+f"((c)[2]), "+f"((c)[3]) \
        : "r"(a0), "r"(a1), "r"(a2), "r"(a3), "r"(b0), "r"(b1))

// ---------------------------------------------------------------------------
// Kernel 0: weight transpose + fp16 convert. W[512,N] -> Wt[N,512] (half)
// ---------------------------------------------------------------------------
__global__ __launch_bounds__(256) void wt_kernel(
    const float* __restrict__ W, __half* __restrict__ Wt, int N)
{
    __shared__ float t[32][33];
    int kb = blockIdx.y * 32, nb = blockIdx.x * 32;
    int tx = threadIdx.x, ty = threadIdx.y;   // 32 x 8
    #pragma unroll
    for (int i = 0; i < 32; i += 8)
        t[ty + i][tx] = W[(size_t)(kb + ty + i) * N + nb + tx];
    __syncthreads();
    #pragma unroll
    for (int i = 0; i < 32; i += 8)
        Wt[(size_t)(nb + ty + i) * 512 + kb + tx] = __float2half_rn(t[tx][ty + i]);
}

// ---------------------------------------------------------------------------
// Kernel 1: GroupNorm -> fp16 output
// ---------------------------------------------------------------------------
__global__ __launch_bounds__(256) void gn_kernel(
    const float* __restrict__ x, const float* __restrict__ gamma,
    const float* __restrict__ beta, __half* __restrict__ xn)
{
    int bg = blockIdx.x;
    int b = bg >> 5, g = bg & 31;
    const float* base = x + (size_t)b * SEQ * CC + g * GSZ;
    int tid = threadIdx.x;

    float sum = 0.f, sq = 0.f;
    #pragma unroll
    for (int i = 0; i < 4; i++) {
        int s = tid + i * 256;
        const float4* p = reinterpret_cast<const float4*>(base + (size_t)s * CC);
        #pragma unroll
        for (int v4 = 0; v4 < 4; v4++) {
            float4 v = p[v4];
            sum += v.x + v.y + v.z + v.w;
            sq  += v.x * v.x + v.y * v.y + v.z * v.z + v.w * v.w;
        }
    }
    #pragma unroll
    for (int off = 16; off; off >>= 1) {
        sum += __shfl_xor_sync(0xFFFFFFFFu, sum, off);
        sq  += __shfl_xor_sync(0xFFFFFFFFu, sq, off);
    }
    __shared__ float red[2][8];
    __shared__ float stats[2];
    int wid = tid >> 5, lid = tid & 31;
    if (lid == 0) { red[0][wid] = sum; red[1][wid] = sq; }
    __syncthreads();
    if (tid == 0) {
        float S = 0.f, Q = 0.f;
        #pragma unroll
        for (int w = 0; w < 8; w++) { S += red[0][w]; Q += red[1][w]; }
        float mu = S * (1.f / 16384.f);
        float var = Q * (1.f / 16384.f) - mu * mu;
        stats[0] = mu;
        stats[1] = rsqrtf(var + 1e-6f);
    }
    __syncthreads();
    float mu = stats[0], rstd = stats[1];

    float ga[GSZ], be[GSZ];
    #pragma unroll
    for (int c = 0; c < GSZ; c++) {
        ga[c] = gamma[g * GSZ + c] * rstd;
        be[c] = beta[g * GSZ + c];
    }
    __half* obase = xn + (size_t)b * SEQ * CC + g * GSZ;
    #pragma unroll
    for (int i = 0; i < 4; i++) {
        int s = tid + i * 256;
        const float4* p = reinterpret_cast<const float4*>(base + (size_t)s * CC);
        __half2* q = reinterpret_cast<__half2*>(obase + (size_t)s * CC);
        #pragma unroll
        for (int v4 = 0; v4 < 4; v4++) {
            float4 v = p[v4];
            int c = v4 * 4;
            float y0 = (v.x - mu) * ga[c + 0] + be[c + 0];
            float y1 = (v.y - mu) * ga[c + 1] + be[c + 1];
            float y2 = (v.z - mu) * ga[c + 2] + be[c + 2];
            float y3 = (v.w - mu) * ga[c + 3] + be[c + 3];
            q[v4 * 2 + 0] = __floats2half2_rn(y0, y1);
            q[v4 * 2 + 1] = __floats2half2_rn(y2, y3);
        }
    }
}

// ---------------------------------------------------------------------------
// Kernel 2: fp16 HMMA GEMM.  C[M,N] = A[M,512](h) @ Wt[N,512](h)^T + bias (+R)
// CTA 128x128, BK=32, cp.async double-buffer, 8 warps, warp tile 32x64.
// HOUT: write __half (no residual), else float (+residual).
// ---------------------------------------------------------------------------
#define GSTRIDE 40

template<bool HOUT>
__global__ __launch_bounds__(256) void gemm_hmma(
    const __half* __restrict__ A, const __half* __restrict__ Wt,
    const float* __restrict__ bias, const float* __restrict__ R,
    void* __restrict__ Cv, int N)
{
    __shared__ __half As[2][128 * GSTRIDE];
    __shared__ __half Bs[2][128 * GSTRIDE];

    int tid = threadIdx.x;
    int lane = tid & 31;
    int wid = tid >> 5;
    int wm = (wid & 3) * 32;
    int wn = (wid >> 2) * 64;
    int bm = blockIdx.y * 128;
    int bn = blockIdx.x * 128;

    float c[2][8][4];
    #pragma unroll
    for (int mi = 0; mi < 2; mi++)
        #pragma unroll
        for (int ni = 0; ni < 8; ni++)
            #pragma unroll
            for (int k = 0; k < 4; k++) c[mi][ni][k] = 0.f;

    auto stage = [&](int s, int buf) {
        const __half* Ag = A + (size_t)bm * 512 + s * 32;
        const __half* Bg = Wt + (size_t)bn * 512 + s * 32;
        #pragma unroll
        for (int i = 0; i < 2; i++) {
            int chunk = tid + i * 256;
            int r = chunk >> 2, cc = chunk & 3;
            uint32_t sa = smem_u32(&As[buf][r * GSTRIDE + cc * 8]);
            CP_ASYNC16(sa, Ag + (size_t)r * 512 + cc * 8);
            uint32_t sbb = smem_u32(&Bs[buf][r * GSTRIDE + cc * 8]);
            CP_ASYNC16(sbb, Bg + (size_t)r * 512 + cc * 8);
        }
    };

    stage(0, 0);
    CP_COMMIT();

    for (int s = 0; s < 16; s++) {
        int buf = s & 1;
        if (s + 1 < 16) {
            stage(s + 1, buf ^ 1);
            CP_COMMIT();
            CP_WAIT(1);
        } else {
            CP_WAIT(0);
        }
        __syncthreads();

        const __half* Ab = As[buf];
        const __half* Bb = Bs[buf];
        #pragma unroll
        for (int kk = 0; kk < 2; kk++) {
            uint32_t a[2][4];
            #pragma unroll
            for (int mi = 0; mi < 2; mi++) {
                int row = wm + mi * 16 + (lane & 7) + ((lane >> 3) & 1) * 8;
                int kc = kk * 16 + ((lane >> 4) & 1) * 8;
                uint32_t addr = smem_u32(&Ab[row * GSTRIDE + kc]);
                LDMATRIX_X4(a[mi][0], a[mi][1], a[mi][2], a[mi][3], addr);
            }
            uint32_t b[8][2];
            #pragma unroll
            for (int bi = 0; bi < 4; bi++) {
                int n = wn + bi * 16 + (lane & 7) + ((lane >> 4) & 1) * 8;
                int kc = kk * 16 + ((lane >> 3) & 1) * 8;
                uint32_t addr = smem_u32(&Bb[n * GSTRIDE + kc]);
                uint32_t r0, r1, r2, r3;
                LDMATRIX_X4(r0, r1, r2, r3, addr);
                b[bi * 2 + 0][0] = r0; b[bi * 2 + 0][1] = r1;
                b[bi * 2 + 1][0] = r2; b[bi * 2 + 1][1] = r3;
            }
            #pragma unroll
            for (int mi = 0; mi < 2; mi++)
                #pragma unroll
                for (int ni = 0; ni < 8; ni++)
                    MMA16816(c[mi][ni], a[mi][0], a[mi][1], a[mi][2], a[mi][3],
                             b[ni][0], b[ni][1]);
        }
        __syncthreads();
    }

    // epilogue
    #pragma unroll
    for (int mi = 0; mi < 2; mi++) {
        int r0 = bm + wm + mi * 16 + (lane >> 2);
        #pragma unroll
        for (int ni = 0; ni < 8; ni++) {
            int col = bn + wn + ni * 8 + (lane & 3) * 2;
            float bx = bias[col], by = bias[col + 1];
            float v00 = c[mi][ni][0] + bx, v01 = c[mi][ni][1] + by;
            float v10 = c[mi][ni][2] + bx, v11 = c[mi][ni][3] + by;
            if (HOUT) {
                __half* C = (__half*)Cv;
                *reinterpret_cast<__half2*>(C + (size_t)r0 * N + col) = __floats2half2_rn(v00, v01);
                *reinterpret_cast<__half2*>(C + (size_t)(r0 + 8) * N + col) = __floats2half2_rn(v10, v11);
            } else {
                float* C = (float*)Cv;
                if (R) {
                    const float2 ra = *reinterpret_cast<const float2*>(R + (size_t)r0 * N + col);
                    const float2 rb = *reinterpret_cast<const float2*>(R + (size_t)(r0 + 8) * N + col);
                    v00 += ra.x; v01 += ra.y; v10 += rb.x; v11 += rb.y;
                }
                *reinterpret_cast<float2*>(C + (size_t)r0 * N + col) = make_float2(v00, v01);
                *reinterpret_cast<float2*>(C + (size_t)(r0 + 8) * N + col) = make_float2(v10, v11);
            }
        }
    }
}

// ---------------------------------------------------------------------------
// Kernel 3: HMMA flash attention.
// CTA = (b, h, 128 q-rows). 8 warps x 16 rows. KV chunks of 64, cp.async
// double-buffered. S=Q@K^T (fp32 accum), online softmax, P@V with P kept
// register-resident (accum->A-fragment identity).
// ---------------------------------------------------------------------------
#define KSTR 72

__global__ __launch_bounds__(256) void attn_hmma(
    const __half* __restrict__ qkv, __half* __restrict__ out)
{
    __shared__ __half Qs[128 * KSTR];
    __shared__ __half Ks[2][64 * KSTR];
    __shared__ __half Vs[2][64 * KSTR];

    int b = blockIdx.z, h = blockIdx.y, qt = blockIdx.x;
    int tid = threadIdx.x, lane = tid & 31, wid = tid >> 5;

    const __half* base = qkv + (size_t)b * SEQ * C3 + h * HD;

    // stage Q (128 rows x 64 halves = 1024 x 16B chunks, 8 chunks/row)
    #pragma unroll
    for (int i = 0; i < 4; i++) {
        int chunk = tid + i * 256;
        int r = chunk >> 3, c8 = (chunk & 7) * 8;
        CP_ASYNC16(smem_u32(&Qs[r * KSTR + c8]),
                   base + (size_t)(qt * 128 + r) * C3 + c8);
    }
    // stage KV chunk 0 (64 rows x 8 chunks = 512 chunks each)
    #pragma unroll
    for (int i = 0; i < 2; i++) {
        int chunk = tid + i * 256;
        int r = chunk >> 3, c8 = (chunk & 7) * 8;
        const __half* kg = base + (size_t)r * C3 + CC + c8;
        CP_ASYNC16(smem_u32(&Ks[0][r * KSTR + c8]), kg);
        CP_ASYNC16(smem_u32(&Vs[0][r * KSTR + c8]), kg + CC);
    }
    CP_COMMIT();

    float o[8][4];
    #pragma unroll
    for (int i = 0; i < 8; i++)
        #pragma unroll
        for (int k = 0; k < 4; k++) o[i][k] = 0.f;
    float mrow0 = -1e30f, mrow1 = -1e30f, lrow0 = 0.f, lrow1 = 0.f;
    uint32_t qf[4][4];

    for (int ch = 0; ch < 16; ch++) {
        int buf = ch & 1;
        if (ch + 1 < 16) {
            #pragma unroll
            for (int i = 0; i < 2; i++) {
                int chunk = tid + i * 256;
                int r = chunk >> 3, c8 = (chunk & 7) * 8;
                const __half* kg = base + (size_t)((ch + 1) * 64 + r) * C3 + CC + c8;
                CP_ASYNC16(smem_u32(&Ks[buf ^ 1][r * KSTR + c8]), kg);
                CP_ASYNC16(smem_u32(&Vs[buf ^ 1][r * KSTR + c8]), kg + CC);
            }
            CP_COMMIT();
            CP_WAIT(1);
        } else {
            CP_WAIT(0);
        }
        __syncthreads();

        if (ch == 0) {
            // load Q fragments once (register-resident thereafter)
            #pragma unroll
            for (int ks = 0; ks < 4; ks++) {
                int row = wid * 16 + (lane & 7) + ((lane >> 3) & 1) * 8;
                int col = ks * 16 + ((lane >> 4) & 1) * 8;
                uint32_t a = smem_u32(&Qs[row * KSTR + col]);
                LDMATRIX_X4(qf[ks][0], qf[ks][1], qf[ks][2], qf[ks][3], a);
            }
        }

        // ---- S = Q @ K^T  (16 rows x 64 cols per warp) ----
        float sacc[8][4];
        #pragma unroll
        for (int j = 0; j < 8; j++)
            #pragma unroll
            for (int k = 0; k < 4; k++) sacc[j][k] = 0.f;

        #pragma unroll
        for (int j = 0; j < 8; j++) {
            uint32_t kf[8];
            uint32_t a0 = smem_u32(&Ks[buf][(8 * j + (lane & 7)) * KSTR + (lane >> 3) * 8]);
            LDMATRIX_X4(kf[0], kf[1], kf[2], kf[3], a0);
            LDMATRIX_X4(kf[4], kf[5], kf[6], kf[7], a0 + 64);  // +32 halves
            #pragma unroll
            for (int ks = 0; ks < 4; ks++)
                MMA16816(sacc[j], qf[ks][0], qf[ks][1], qf[ks][2], qf[ks][3],
                         kf[2 * ks], kf[2 * ks + 1]);
        }

        // ---- online softmax (scale^2 = 1/64 folded here) ----
        const float sc = 1.0f / 64.0f;
        #pragma unroll
        for (int j = 0; j < 8; j++)
            #pragma unroll
            for (int k = 0; k < 4; k++) sacc[j][k] *= sc;

        float mx0 = mrow0, mx1 = mrow1;
        #pragma unroll
        for (int j = 0; j < 8; j++) {
            mx0 = fmaxf(mx0, fmaxf(sacc[j][0], sacc[j][1]));
            mx1 = fmaxf(mx1, fmaxf(sacc[j][2], sacc[j][3]));
        }
        mx0 = fmaxf(mx0, __shfl_xor_sync(0xFFFFFFFFu, mx0, 1));
        mx0 = fmaxf(mx0, __shfl_xor_sync(0xFFFFFFFFu, mx0, 2));
        mx1 = fmaxf(mx1, __shfl_xor_sync(0xFFFFFFFFu, mx1, 1));
        mx1 = fmaxf(mx1, __shfl_xor_sync(0xFFFFFFFFu, mx1, 2));

        float corr0 = __expf(mrow0 - mx0);
        float corr1 = __expf(mrow1 - mx1);
        mrow0 = mx0; mrow1 = mx1;
        lrow0 *= corr0; lrow1 *= corr1;
        #pragma unroll
        for (int nd = 0; nd < 8; nd++) {
            o[nd][0] *= corr0; o[nd][1] *= corr0;
            o[nd][2] *= corr1; o[nd][3] *= corr1;
        }

        uint32_t pf[4][4];
        #pragma unroll
        for (int jp = 0; jp < 4; jp++) {
            float p00 = __expf(sacc[2 * jp][0] - mx0);
            float p01 = __expf(sacc[2 * jp][1] - mx0);
            float p10 = __expf(sacc[2 * jp][2] - mx1);
            float p11 = __expf(sacc[2 * jp][3] - mx1);
            float p20 = __expf(sacc[2 * jp + 1][0] - mx0);
            float p21 = __expf(sacc[2 * jp + 1][1] - mx0);
            float p30 = __expf(sacc[2 * jp + 1][2] - mx1);
            float p31 = __expf(sacc[2 * jp + 1][3] - mx1);
            lrow0 += p00 + p01 + p20 + p21;
            lrow1 += p10 + p11 + p30 + p31;
            pf[jp][0] = f22u(p00, p01);
            pf[jp][1] = f22u(p10, p11);
            pf[jp][2] = f22u(p20, p21);
            pf[jp][3] = f22u(p30, p31);
        }

        // ---- O += P @ V ----
        #pragma unroll
        for (int ks = 0; ks < 4; ks++) {
            #pragma unroll
            for (int np = 0; np < 4; np++) {
                uint32_t v0, v1, v2, v3;
                int row = 16 * ks + ((lane >> 3) & 1) * 8 + (lane & 7);
                int col = np * 16 + (lane >> 4) * 8;
                LDMATRIX_X4_T(v0, v1, v2, v3, smem_u32(&Vs[buf][row * KSTR + col]));
                MMA16816(o[2 * np], pf[ks][0], pf[ks][1], pf[ks][2], pf[ks][3], v0, v1);
                MMA16816(o[2 * np + 1], pf[ks][0], pf[ks][1], pf[ks][2], pf[ks][3], v2, v3);
            }
        }
        __syncthreads();
    }

    // ---- finalize: reduce l over quad, normalize, store fp16 ----
    lrow0 += __shfl_xor_sync(0xFFFFFFFFu, lrow0, 1);
    lrow0 += __shfl_xor_sync(0xFFFFFFFFu, lrow0, 2);
    lrow1 += __shfl_xor_sync(0xFFFFFFFFu, lrow1, 1);
    lrow1 += __shfl_xor_sync(0xFFFFFFFFu, lrow1, 2);
    float inv0 = 1.0f / lrow0, inv1 = 1.0f / lrow1;

    int r0 = qt * 128 + wid * 16 + (lane >> 2);
    __half* ob = out + (size_t)b * SEQ * CC + h * HD;
    #pragma unroll
    for (int nd = 0; nd < 8; nd++) {
        int col = nd * 8 + (lane & 3) * 2;
        *reinterpret_cast<__half2*>(ob + (size_t)r0 * CC + col) =
            __floats2half2_rn(o[nd][0] * inv0, o[nd][1] * inv0);
        *reinterpret_cast<__half2*>(ob + (size_t)(r0 + 8) * CC + col) =
            __floats2half2_rn(o[nd][2] * inv1, o[nd][3] * inv1);
    }
}

// ---------------------------------------------------------------------------
// Launch
// ---------------------------------------------------------------------------
extern "C" void kernel_launch(void* const* d_in, const int* in_sizes, int n_in,
                              void* d_out, int out_size)
{
    const float* x        = (const float*)d_in[0];
    const float* gn_scale = (const float*)d_in[1];
    const float* gn_bias  = (const float*)d_in[2];
    const float* w_qkv    = (const float*)d_in[3];
    const float* b_qkv    = (const float*)d_in[4];
    const float* w_out    = (const float*)d_in[5];
    const float* b_out    = (const float*)d_in[6];
    float* out            = (float*)d_out;

    __half* xn;   cudaGetSymbolAddress((void**)&xn,   g_xn_h);
    __half* qkv;  cudaGetSymbolAddress((void**)&qkv,  g_qkv_h);
    __half* attn; cudaGetSymbolAddress((void**)&attn, g_attn_h);
    __half* wtq;  cudaGetSymbolAddress((void**)&wtq,  g_wth_qkv);
    __half* wto;  cudaGetSymbolAddress((void**)&wto,  g_wth_out);

    // 0) weight transposes (fp16)
    {
        dim3 blk(32, 8);
        wt_kernel<<<dim3(C3 / 32, 16), blk>>>(w_qkv, wtq, C3);
        wt_kernel<<<dim3(CC / 32, 16), blk>>>(w_out, wto, CC);
    }

    // 1) GroupNorm -> fp16
    gn_kernel<<<BB * NG, 256>>>(x, gn_scale, gn_bias, xn);

    // 2) QKV projection (HMMA, fp16 out)
    gemm_hmma<true><<<dim3(C3 / 128, (BB * SEQ) / 128), 256>>>(xn, wtq, b_qkv, nullptr, qkv, C3);

    // 3) Attention (HMMA flash)
    attn_hmma<<<dim3(SEQ / 128, NH, BB), 256>>>(qkv, attn);

    // 4) Output projection + bias + residual (HMMA, fp32 out)
    gemm_hmma<false><<<dim3(CC / 128, (BB * SEQ) / 128), 256>>>(attn, wto, b_out, x, out, CC);
}